// round 7
// baseline (speedup 1.0000x reference)
#include <cuda_runtime.h>
#include <cuda_fp16.h>

// HybridEulerIntegrator: a_{t+1} = a_t + C * (MLP([x_t, a_t]))^3
// MLP 2 -> 64 (tanh) -> 1 in packed f16x2, f32 recurrence state.
// MUFU/FMA pipe split: per thread, 2 half2 pairs use tanh.approx.f16x2 (MUFU),
// 2 pairs use ex2.approx.f16x2 + degree-5 poly for (1-e)/(1+e) (mostly FMA pipe).
// TPE=8, BLOCK=64 (2048 blocks -> even 14/13 per-SM balance).

#define T_STEPS 2048
#define BATCH   16384
#define HIDDEN  64
#define TPE     8
#define PAIRS   4
#define BLOCK   64
#define W2SCALE 0.125f

__device__ __forceinline__ __half2 tanh_h2(__half2 v) {
    unsigned r, in = *(unsigned*)&v;
    asm("tanh.approx.f16x2 %0, %1;" : "=r"(r) : "r"(in));
    return *(__half2*)&r;
}

__device__ __forceinline__ __half2 ex2_h2(__half2 v) {
    unsigned r, in = *(unsigned*)&v;
    asm("ex2.approx.f16x2 %0, %1;" : "=r"(r) : "r"(in));
    return *(__half2*)&r;
}

// tanh via e = 2^(-2*log2(e)*|p|);  tanh(|p|) = (1-e)/(1+e) = h(u), u = 2e-1.
// h(u) = c0 + c1 u + ... + c5 u^5 (Chebyshev projection of (1-u)/(3+u), |err| < 1e-4).
__device__ __forceinline__ __half2 tanh_poly_h2(__half2 p) {
    const __half2 kScale = __float2half2_rn(-2.8853900817779268f); // -2/ln2... = -2*log2(e)
    const __half2 c5 = __float2half2_rn(-0.00672821f);
    const __half2 c4 = __float2half2_rn( 0.0196078f);
    const __half2 c3 = __float2half2_rn(-0.0487297f);
    const __half2 c2 = __float2half2_rn( 0.146914f);
    const __half2 c1 = __float2half2_rn(-0.444529f);
    const __half2 c0 = __float2half2_rn( 0.333404f);
    const __half2 two  = __float2half2_rn(2.0f);
    const __half2 mone = __float2half2_rn(-1.0f);

    __half2 q = __habs2(p);
    __half2 e = ex2_h2(__hmul2(q, kScale));      // e = exp(-2|p|) in (0,1]
    __half2 u = __hfma2(e, two, mone);           // u = 2e - 1 in [-1,1]
    __half2 r = __hfma2(u, c5, c4);
    r = __hfma2(u, r, c3);
    r = __hfma2(u, r, c2);
    r = __hfma2(u, r, c1);
    r = __hfma2(u, r, c0);                       // r = tanh(|p|) >= 0
    // copysign(r, p): r has clear sign bits, OR in p's sign bits (one LOP3).
    unsigned ru = *(unsigned*)&r, pu = *(unsigned*)&p;
    unsigned outu = ru | (pu & 0x80008000u);
    return *(__half2*)&outu;
}

__global__ void __launch_bounds__(BLOCK)
hybrid_euler_kernel(const float* __restrict__ x,
                    const float* __restrict__ a0,
                    const float* __restrict__ W1,
                    const float* __restrict__ b1,
                    const float* __restrict__ W2,
                    const float* __restrict__ b2,
                    float* __restrict__ out)
{
    const int tid = blockIdx.x * BLOCK + threadIdx.x;
    const int e   = tid >> 3;
    const int s   = tid & 7;

    __half2 w1x[PAIRS], w1a[PAIRS], b1h[PAIRS], w2h[PAIRS];
#pragma unroll
    for (int p = 0; p < PAIRS; p++) {
        const int j = s * (2 * PAIRS) + 2 * p;
        w1x[p] = __floats2half2_rn(W1[j],           W1[j + 1]);
        w1a[p] = __floats2half2_rn(W1[HIDDEN + j],  W1[HIDDEN + j + 1]);
        b1h[p] = __floats2half2_rn(b1[j],           b1[j + 1]);
        w2h[p] = __floats2half2_rn(W2[j] * W2SCALE, W2[j + 1] * W2SCALE);
    }
    const float bias2 = b2[0];

    float a = a0[e];
    const float* xp = x + e;
    float*       op = out + e;

    // x-part of pre-activation, computed one step ahead (off the a-chain).
    __half2 xpart[PAIRS];
    {
        const __half2 xh0 = __float2half2_rn(__ldg(xp));
#pragma unroll
        for (int p = 0; p < PAIRS; p++)
            xpart[p] = __hfma2(xh0, w1x[p], b1h[p]);
    }

    for (int t = 0; t < T_STEPS; t++) {
        float xt_next = 0.0f;
        if (t + 1 < T_STEPS) xt_next = __ldg(xp + BATCH);
        xp += BATCH;

        const __half2 ah = __float2half2_rn(a);

        __half2 pre0 = __hfma2(ah, w1a[0], xpart[0]);
        __half2 pre1 = __hfma2(ah, w1a[1], xpart[1]);
        __half2 pre2 = __hfma2(ah, w1a[2], xpart[2]);
        __half2 pre3 = __hfma2(ah, w1a[3], xpart[3]);

        // Pipe split: pairs 0,1 -> MUFU tanh; pairs 2,3 -> ex2 + FMA poly.
        __half2 acc0 = __hmul2(tanh_h2(pre0),      w2h[0]);
        __half2 acc1 = __hmul2(tanh_h2(pre1),      w2h[1]);
        acc0 = __hfma2(tanh_poly_h2(pre2), w2h[2], acc0);
        acc1 = __hfma2(tanh_poly_h2(pre3), w2h[3], acc1);

        // Off-chain: next step's x-part.
        const __half2 xhn = __float2half2_rn(xt_next);
#pragma unroll
        for (int p = 0; p < PAIRS; p++)
            xpart[p] = __hfma2(xhn, w1x[p], b1h[p]);

        const __half2 accs = __hadd2(acc0, acc1);
        const float2 f2 = __half22float2(accs);
        float dk = f2.x + f2.y;

        dk += __shfl_xor_sync(0xFFFFFFFFu, dk, 1);
        dk += __shfl_xor_sync(0xFFFFFFFFu, dk, 2);
        dk += __shfl_xor_sync(0xFFFFFFFFu, dk, 4);
        dk = fmaf(dk, 8.0f, bias2);

        const float dk2 = dk * dk;
        a = fmaf(0.001f * dk, dk2, a);

        if (s == 0) *op = a;
        op += BATCH;
    }
}

extern "C" void kernel_launch(void* const* d_in, const int* in_sizes, int n_in,
                              void* d_out, int out_size)
{
    const float* x  = (const float*)d_in[0];
    const float* a0 = (const float*)d_in[1];
    const float* W1 = (const float*)d_in[2];
    const float* b1 = (const float*)d_in[3];
    const float* W2 = (const float*)d_in[4];
    const float* b2 = (const float*)d_in[5];
    float* out = (float*)d_out;

    const int total_threads = BATCH * TPE;           // 131072
    const int grid = total_threads / BLOCK;          // 2048 blocks
    hybrid_euler_kernel<<<grid, BLOCK>>>(x, a0, W1, b1, W2, b2, out);
}

// round 8
// speedup vs baseline: 1.2327x; 1.2327x over previous
#include <cuda_runtime.h>
#include <math.h>

// HybridEulerIntegrator via function tabulation.
// dk(x,a) = sum_j W2[j]*tanh(W1[0][j]*x + W1[1][j]*a + b1[j]) + b2 is a fixed
// 2D scalar function. Build kernel tabulates it as: per a-bin (log-warped grid
// s = sign(a)*log2(1+|a|), 6144 bins over s in [-12,12]) a degree-6 polynomial
// in x (Chebyshev nodes on [0,1]). Main kernel: the 2048-step scan per element
// is 4 LDS.128 + Horner + lerp + cube per step -- no transcendentals.

#define T_STEPS 2048
#define BATCH   16384
#define HIDDEN  64
#define BINS    6144
#define SRANGE  12.0f
#define NDEG    7              // 7 coefficients (degree 6)

// Static device scratch (allocation-free rule).
__device__ float4 g_tabA[BINS];   // coeffs c0..c3
__device__ float4 g_tabB[BINS];   // coeffs c4..c6, pad

// ---------------------------------------------------------------------------
// Build: one thread per a-bin. Evaluate dk at 7 Chebyshev x-nodes (exact f32
// tanh), Newton divided differences -> monomial coefficients.
// ---------------------------------------------------------------------------
__global__ void build_table_kernel(const float* __restrict__ W1,
                                   const float* __restrict__ b1,
                                   const float* __restrict__ W2,
                                   const float* __restrict__ b2)
{
    const int bin = blockIdx.x * blockDim.x + threadIdx.x;
    if (bin >= BINS) return;

    const float ds = (2.0f * SRANGE) / (float)(BINS - 1);
    const float s  = -SRANGE + bin * ds;
    const float am = exp2f(fabsf(s)) - 1.0f;         // |a| for this bin
    const float a  = (s < 0.0f) ? -am : am;

    // Chebyshev nodes on [0,1]
    float xn[NDEG], v[NDEG];
#pragma unroll
    for (int k = 0; k < NDEG; k++)
        xn[k] = 0.5f + 0.5f * cosf((2.0f * k + 1.0f) * (float)M_PI / 14.0f);

    const float bias2 = b2[0];
#pragma unroll
    for (int k = 0; k < NDEG; k++) {
        float acc = bias2;
        for (int j = 0; j < HIDDEN; j++) {
            float pre = fmaf(W1[j], xn[k], fmaf(W1[HIDDEN + j], a, b1[j]));
            acc = fmaf(W2[j], tanhf(pre), acc);
        }
        v[k] = acc;
    }

    // Newton divided differences (in place).
#pragma unroll
    for (int j = 1; j < NDEG; j++)
#pragma unroll
        for (int i = NDEG - 1; i >= j; i--)
            v[i] = (v[i] - v[i - 1]) / (xn[i] - xn[i - j]);

    // Newton -> monomial: p = v[6]; for k=5..0: p = p*(x - xn[k]) + v[k]
    float m[NDEG];
    m[0] = v[NDEG - 1];
#pragma unroll
    for (int i = 1; i < NDEG; i++) m[i] = 0.0f;
#pragma unroll
    for (int k = NDEG - 2; k >= 0; k--) {
#pragma unroll
        for (int i = NDEG - 1; i >= 1; i--)
            m[i] = m[i - 1] - xn[k] * m[i];
        m[0] = v[k] - xn[k] * m[0];
    }

    g_tabA[bin] = make_float4(m[0], m[1], m[2], m[3]);
    g_tabB[bin] = make_float4(m[4], m[5], m[6], 0.0f);
}

// ---------------------------------------------------------------------------
// Main scan: table in SMEM, one thread per batch element.
// ---------------------------------------------------------------------------
#define MBLOCK 128

__global__ void __launch_bounds__(MBLOCK)
scan_kernel(const float* __restrict__ x,
            const float* __restrict__ a0,
            float* __restrict__ out)
{
    extern __shared__ float4 sm[];          // [0..BINS) = A, [BINS..2*BINS) = B
    // Cooperative load of the table (192 KB) into SMEM.
    for (int i = threadIdx.x; i < BINS; i += MBLOCK) {
        sm[i]        = g_tabA[i];
        sm[BINS + i] = g_tabB[i];
    }
    __syncthreads();

    const int e = blockIdx.x * MBLOCK + threadIdx.x;

    const float ds     = (2.0f * SRANGE) / (float)(BINS - 1);
    const float scale  = 1.0f / ds;
    const float offset = SRANGE * scale;
    const float MAGIC  = 12582912.0f;       // 2^23 + 2^22

    float a = a0[e];
    const float* xp = x + e;
    float*       op = out + e;

    float xt = *xp;                          // prefetched x_t

    for (int t = 0; t < T_STEPS; t++) {
        // Pipelined load of x_{t+1} (address independent of a).
        float xt_next = 0.0f;
        if (t + 1 < T_STEPS) xt_next = __ldg(xp + BATCH);
        xp += BATCH;

        // Index into log-warped a-grid: s = sign(a)*log2(1+|a|)
        float l = __log2f(1.0f + fabsf(a));
        float s = copysignf(l, a);
        float u = fmaf(s, scale, offset);
        u = fminf(fmaxf(u, 0.0f), (float)(BINS - 2));
        float mg = u + MAGIC;                       // round-to-nearest int in mantissa
        int   i  = __float_as_int(mg) & 0xFFFF;     // BINS < 65536
        float f  = u - (mg - MAGIC);                // in [-0.5, 0.5]

        float4 A0 = sm[i],     B0 = sm[BINS + i];
        float4 A1 = sm[i + 1], B1 = sm[BINS + i + 1];

        // Horner degree-6 in x for both rows (parallel chains), then lerp in s.
        float r0 = B0.z;
        r0 = fmaf(r0, xt, B0.y); r0 = fmaf(r0, xt, B0.x);
        r0 = fmaf(r0, xt, A0.w); r0 = fmaf(r0, xt, A0.z);
        r0 = fmaf(r0, xt, A0.y); r0 = fmaf(r0, xt, A0.x);
        float r1 = B1.z;
        r1 = fmaf(r1, xt, B1.y); r1 = fmaf(r1, xt, B1.x);
        r1 = fmaf(r1, xt, A1.w); r1 = fmaf(r1, xt, A1.z);
        r1 = fmaf(r1, xt, A1.y); r1 = fmaf(r1, xt, A1.x);

        float dk = fmaf(f, r1 - r0, r0);

        // a += C * dk^3
        a = fmaf(0.001f * dk, dk * dk, a);

        *op = a;
        op += BATCH;
        xt = xt_next;
    }
}

extern "C" void kernel_launch(void* const* d_in, const int* in_sizes, int n_in,
                              void* d_out, int out_size)
{
    const float* x  = (const float*)d_in[0];
    const float* a0 = (const float*)d_in[1];
    const float* W1 = (const float*)d_in[2];
    const float* b1 = (const float*)d_in[3];
    const float* W2 = (const float*)d_in[4];
    const float* b2 = (const float*)d_in[5];
    float* out = (float*)d_out;

    build_table_kernel<<<(BINS + 127) / 128, 128>>>(W1, b1, W2, b2);

    const size_t smem = 2u * BINS * sizeof(float4);   // 196608 B
    static int smem_set = 0;
    if (!smem_set) {
        cudaFuncSetAttribute(scan_kernel,
                             cudaFuncAttributeMaxDynamicSharedMemorySize,
                             (int)smem);
        smem_set = 1;
    }
    scan_kernel<<<BATCH / MBLOCK, MBLOCK, smem>>>(x, a0, out);
}

// round 10
// speedup vs baseline: 2.2439x; 1.8204x over previous
#include <cuda_runtime.h>
#include <math.h>

// HybridEulerIntegrator via function tabulation + deep x prefetch.
// dk(x,a) tabulated per a-bin (log-warped, 6144 bins) as degree-6 poly in x.
// Scan: one thread per element; time loop unrolled by PF=8 with a register
// double-buffer on the x stream (MLP=8) so the ~577-cyc DRAM latency is
// amortized across 8 steps instead of exposed every step.
// R9 bug fixed: prefetch offsets are tile-relative (xp advances per tile).

#define T_STEPS 2048
#define BATCH   16384
#define HIDDEN  64
#define BINS    6144
#define SRANGE  12.0f
#define NDEG    7
#define PF      8              // prefetch depth / time unroll

__device__ float4 g_tabA[BINS];
__device__ float4 g_tabB[BINS];

// ---------------------------------------------------------------------------
// Build: one thread per a-bin (exact f32 tanh at 7 Chebyshev x-nodes ->
// Newton divided differences -> monomial coefficients).
// ---------------------------------------------------------------------------
__global__ void build_table_kernel(const float* __restrict__ W1,
                                   const float* __restrict__ b1,
                                   const float* __restrict__ W2,
                                   const float* __restrict__ b2)
{
    const int bin = blockIdx.x * blockDim.x + threadIdx.x;
    if (bin >= BINS) return;

    const float ds = (2.0f * SRANGE) / (float)(BINS - 1);
    const float s  = -SRANGE + bin * ds;
    const float am = exp2f(fabsf(s)) - 1.0f;
    const float a  = (s < 0.0f) ? -am : am;

    float xn[NDEG], v[NDEG];
#pragma unroll
    for (int k = 0; k < NDEG; k++)
        xn[k] = 0.5f + 0.5f * cosf((2.0f * k + 1.0f) * (float)M_PI / 14.0f);

    const float bias2 = b2[0];
#pragma unroll
    for (int k = 0; k < NDEG; k++) {
        float acc = bias2;
        for (int j = 0; j < HIDDEN; j++) {
            float pre = fmaf(W1[j], xn[k], fmaf(W1[HIDDEN + j], a, b1[j]));
            acc = fmaf(W2[j], tanhf(pre), acc);
        }
        v[k] = acc;
    }

#pragma unroll
    for (int j = 1; j < NDEG; j++)
#pragma unroll
        for (int i = NDEG - 1; i >= j; i--)
            v[i] = (v[i] - v[i - 1]) / (xn[i] - xn[i - j]);

    float m[NDEG];
    m[0] = v[NDEG - 1];
#pragma unroll
    for (int i = 1; i < NDEG; i++) m[i] = 0.0f;
#pragma unroll
    for (int k = NDEG - 2; k >= 0; k--) {
#pragma unroll
        for (int i = NDEG - 1; i >= 1; i--)
            m[i] = m[i - 1] - xn[k] * m[i];
        m[0] = v[k] - xn[k] * m[0];
    }

    g_tabA[bin] = make_float4(m[0], m[1], m[2], m[3]);
    g_tabB[bin] = make_float4(m[4], m[5], m[6], 0.0f);
}

// ---------------------------------------------------------------------------
// Main scan.
// ---------------------------------------------------------------------------
#define MBLOCK 128

__global__ void __launch_bounds__(MBLOCK)
scan_kernel(const float* __restrict__ x,
            const float* __restrict__ a0,
            float* __restrict__ out)
{
    extern __shared__ float4 sm[];          // [0..BINS)=A, [BINS..2*BINS)=B
    for (int i = threadIdx.x; i < BINS; i += MBLOCK) {
        sm[i]        = g_tabA[i];
        sm[BINS + i] = g_tabB[i];
    }
    __syncthreads();

    const int e = blockIdx.x * MBLOCK + threadIdx.x;

    const float ds     = (2.0f * SRANGE) / (float)(BINS - 1);
    const float scale  = 1.0f / ds;
    const float offset = SRANGE * scale;
    const float MAGIC  = 12582912.0f;       // 2^23 + 2^22

    float a = a0[e];
    const float* xp = x + e;                // base of current tile's x column
    float*       op = out + e;

    // Prologue: fill current buffer with x[0..PF-1].
    float cur[PF], nxt[PF];
#pragma unroll
    for (int k = 0; k < PF; k++)
        cur[k] = __ldg(xp + k * BATCH);

    for (int tb = 0; tb < T_STEPS; tb += PF) {
        // Issue next tile's loads first (tile-relative: xp tracks tile tb).
        if (tb + PF < T_STEPS) {
#pragma unroll
            for (int k = 0; k < PF; k++)
                nxt[k] = __ldg(xp + (PF + k) * BATCH);
        }

#pragma unroll
        for (int k = 0; k < PF; k++) {
            const float xt = cur[k];

            // Index into log-warped a-grid: s = sign(a)*log2(1+|a|)
            float l = __log2f(1.0f + fabsf(a));
            float s = copysignf(l, a);
            float u = fmaf(s, scale, offset);
            u = fminf(fmaxf(u, 0.0f), (float)(BINS - 2));
            float mg = u + MAGIC;
            int   i  = __float_as_int(mg) & 0xFFFF;
            float f  = u - (mg - MAGIC);           // in [-0.5, 0.5]

            float4 A0 = sm[i],     B0 = sm[BINS + i];
            float4 A1 = sm[i + 1], B1 = sm[BINS + i + 1];

            float r0 = B0.z;
            r0 = fmaf(r0, xt, B0.y); r0 = fmaf(r0, xt, B0.x);
            r0 = fmaf(r0, xt, A0.w); r0 = fmaf(r0, xt, A0.z);
            r0 = fmaf(r0, xt, A0.y); r0 = fmaf(r0, xt, A0.x);
            float r1 = B1.z;
            r1 = fmaf(r1, xt, B1.y); r1 = fmaf(r1, xt, B1.x);
            r1 = fmaf(r1, xt, A1.w); r1 = fmaf(r1, xt, A1.z);
            r1 = fmaf(r1, xt, A1.y); r1 = fmaf(r1, xt, A1.x);

            float dk = fmaf(f, r1 - r0, r0);

            a = fmaf(0.001f * dk, dk * dk, a);

            op[k * (size_t)BATCH] = a;
        }

#pragma unroll
        for (int k = 0; k < PF; k++) cur[k] = nxt[k];
        xp += PF * BATCH;
        op += PF * (size_t)BATCH;
    }
}

extern "C" void kernel_launch(void* const* d_in, const int* in_sizes, int n_in,
                              void* d_out, int out_size)
{
    const float* x  = (const float*)d_in[0];
    const float* a0 = (const float*)d_in[1];
    const float* W1 = (const float*)d_in[2];
    const float* b1 = (const float*)d_in[3];
    const float* W2 = (const float*)d_in[4];
    const float* b2 = (const float*)d_in[5];
    float* out = (float*)d_out;

    build_table_kernel<<<(BINS + 127) / 128, 128>>>(W1, b1, W2, b2);

    const size_t smem = 2u * BINS * sizeof(float4);   // 196608 B
    static int smem_set = 0;
    if (!smem_set) {
        cudaFuncSetAttribute(scan_kernel,
                             cudaFuncAttributeMaxDynamicSharedMemorySize,
                             (int)smem);
        smem_set = 1;
    }
    scan_kernel<<<BATCH / MBLOCK, MBLOCK, smem>>>(x, a0, out);
}

// round 12
// speedup vs baseline: 3.3537x; 1.4946x over previous
#include <cuda_runtime.h>
#include <math.h>

// HybridEulerIntegrator via tabulated dk(x,a), chain-optimized scan.
// Table: 2 x-segments x 6144 rows (3072 |a| mantissa-bins x 2 signs), each row
// a degree-3 poly in x (float4). a-index comes straight from the float bits of
// v=1+|a| (exponent + top-8 mantissa bits = log-warped bins; no MUFU on chain).
// R11 bug fixed: within-bin lerp fraction uses bits[14:0] placed at the TOP of
// the mantissa ((bits&0x7FFF)<<8), giving fw in [0,1).

#define T_STEPS 2048
#define BATCH   16384
#define HIDDEN  64
#define NROWS   6144            // rows per x-segment (3072 neg + 3072 pos)
#define NPOLY   (2 * NROWS)     // 12288 cubics
#define PF      8

__device__ float  g_nodes[NPOLY * 4];   // staging: dk at 4 x-nodes per poly
__device__ float4 g_tab[NPOLY];         // cubic coeffs c0..c3

// v(k) for mantissa-bin edge k in [0,3072): 2^(k>>8) * (1 + (k&255)/256)
__device__ __forceinline__ float edge_v(int k) {
    return exp2f((float)(k >> 8)) * (1.0f + (float)(k & 255) * (1.0f / 256.0f));
}

// a for table row r in [0, NROWS): r>=3072 -> idx=r-3072 (a>=0);
// r<3072 -> idx'=3071-r (a<0).  (Matches scan's base = 3072+(idx^sgn)+sgn.)
__device__ __forceinline__ float row_to_a(int r) {
    if (r >= 3072) return  edge_v(r - 3072) - 1.0f;
    else           return -(edge_v(3071 - r) - 1.0f);
}

__device__ __forceinline__ float node_x(int seg, int node) {
    const float lo = 0.5f * (float)seg;
    return lo + 0.5f * (0.5f + 0.5f * cosf((2.0f * node + 1.0f) * (float)M_PI / 8.0f));
}

// ---------------------------------------------------------------------------
// Build 1: one thread per (poly, node) -> dk value. 49152 threads.
// ---------------------------------------------------------------------------
__global__ void build_eval_kernel(const float* __restrict__ W1,
                                  const float* __restrict__ b1,
                                  const float* __restrict__ W2,
                                  const float* __restrict__ b2)
{
    const int tid = blockIdx.x * blockDim.x + threadIdx.x;
    if (tid >= NPOLY * 4) return;
    const int poly = tid >> 2;
    const int node = tid & 3;
    const int seg  = poly / NROWS;
    const int row  = poly - seg * NROWS;

    const float a = row_to_a(row);
    const float x = node_x(seg, node);

    float acc = b2[0];
    for (int j = 0; j < HIDDEN; j++) {
        float pre = fmaf(W1[j], x, fmaf(W1[HIDDEN + j], a, b1[j]));
        acc = fmaf(W2[j], tanhf(pre), acc);
    }
    g_nodes[tid] = acc;
}

// ---------------------------------------------------------------------------
// Build 2: one thread per poly -> fit cubic (Newton DD -> monomial).
// ---------------------------------------------------------------------------
__global__ void build_fit_kernel()
{
    const int poly = blockIdx.x * blockDim.x + threadIdx.x;
    if (poly >= NPOLY) return;
    const int seg = poly / NROWS;

    float xn[4], v[4];
#pragma unroll
    for (int k = 0; k < 4; k++) {
        xn[k] = node_x(seg, k);
        v[k]  = g_nodes[poly * 4 + k];
    }
#pragma unroll
    for (int j = 1; j < 4; j++)
#pragma unroll
        for (int i = 3; i >= j; i--)
            v[i] = (v[i] - v[i - 1]) / (xn[i] - xn[i - j]);

    float m[4];
    m[0] = v[3]; m[1] = 0.0f; m[2] = 0.0f; m[3] = 0.0f;
#pragma unroll
    for (int k = 2; k >= 0; k--) {
#pragma unroll
        for (int i = 3; i >= 1; i--)
            m[i] = m[i - 1] - xn[k] * m[i];
        m[0] = v[k] - xn[k] * m[0];
    }
    g_tab[poly] = make_float4(m[0], m[1], m[2], m[3]);
}

// ---------------------------------------------------------------------------
// Scan.
// ---------------------------------------------------------------------------
#define MBLOCK 128

__global__ void __launch_bounds__(MBLOCK)
scan_kernel(const float* __restrict__ x,
            const float* __restrict__ a0,
            float* __restrict__ out)
{
    extern __shared__ float4 sm[];        // [seg*NROWS + row]
    for (int i = threadIdx.x; i < NPOLY; i += MBLOCK)
        sm[i] = g_tab[i];
    __syncthreads();

    const int e = blockIdx.x * MBLOCK + threadIdx.x;

    float a = a0[e];
    const float* xp = x + e;
    float*       op = out + e;

    float cur[PF], nxt[PF];
#pragma unroll
    for (int k = 0; k < PF; k++)
        cur[k] = __ldg(xp + k * BATCH);

    for (int tb = 0; tb < T_STEPS; tb += PF) {
        if (tb + PF < T_STEPS) {
#pragma unroll
            for (int k = 0; k < PF; k++)
                nxt[k] = __ldg(xp + (PF + k) * BATCH);
        }

        // Off-chain per-x precompute: x^2 and (3072 + segment row offset).
        float xsq[PF];
        int   segbase[PF];
#pragma unroll
        for (int k = 0; k < PF; k++) {
            xsq[k]     = cur[k] * cur[k];
            segbase[k] = 3072 + ((cur[k] >= 0.5f) ? NROWS : 0);
        }

#pragma unroll
        for (int k = 0; k < PF; k++) {
            const float xt = cur[k];

            // --- critical chain: a -> row index -> 2x LDS -> poly -> lerp -> a ---
            const float v    = fminf(fmaf(fabsf(a), 1.0f, 1.0f), 4064.0f);
            const int   bits = __float_as_int(v);
            const int   idx  = (bits >> 15) - (127 << 8);          // 0..3067
            const int   sgn  = __float_as_int(a) >> 31;            // 0 or -1
            const int   i0   = (idx ^ sgn) + segbase[k] + sgn;     // lerp row pair (i0, i0+1)

            const float4 A0 = sm[i0];
            const float4 A1 = sm[i0 + 1];

            // Off the LDS latency: fraction within the bin (mirrored for a<0).
            // bits[14:0] are the sub-bin mantissa bits; splice them at the TOP
            // of a [1,2) float's mantissa -> fw in [0,1).
            const float fw = __int_as_float(((bits & 0x7FFF) << 8) | 0x3F800000) - 1.0f;
            const float fs = (sgn != 0) ? (1.0f - fw) : fw;

            // Cubic eval, depth-2 FMA tree (x, x^2 precomputed off-chain).
            const float r0 = fmaf(fmaf(A0.w, xt, A0.z), xsq[k], fmaf(A0.y, xt, A0.x));
            const float r1 = fmaf(fmaf(A1.w, xt, A1.z), xsq[k], fmaf(A1.y, xt, A1.x));
            const float dk = fmaf(fs, r1 - r0, r0);

            a = fmaf(0.001f * dk, dk * dk, a);

            op[k * (size_t)BATCH] = a;
        }

#pragma unroll
        for (int k = 0; k < PF; k++) cur[k] = nxt[k];
        xp += PF * BATCH;
        op += PF * (size_t)BATCH;
    }
}

extern "C" void kernel_launch(void* const* d_in, const int* in_sizes, int n_in,
                              void* d_out, int out_size)
{
    const float* x  = (const float*)d_in[0];
    const float* a0 = (const float*)d_in[1];
    const float* W1 = (const float*)d_in[2];
    const float* b1 = (const float*)d_in[3];
    const float* W2 = (const float*)d_in[4];
    const float* b2 = (const float*)d_in[5];
    float* out = (float*)d_out;

    build_eval_kernel<<<(NPOLY * 4 + 127) / 128, 128>>>(W1, b1, W2, b2);
    build_fit_kernel<<<(NPOLY + 127) / 128, 128>>>();

    const size_t smem = (size_t)NPOLY * sizeof(float4);   // 196608 B
    static int smem_set = 0;
    if (!smem_set) {
        cudaFuncSetAttribute(scan_kernel,
                             cudaFuncAttributeMaxDynamicSharedMemorySize,
                             (int)smem);
        smem_set = 1;
    }
    scan_kernel<<<BATCH / MBLOCK, MBLOCK, smem>>>(x, a0, out);
}